// round 9
// baseline (speedup 1.0000x reference)
#include <cuda_runtime.h>
#include <cuda_bf16.h>
#include <cstdint>

#define KK 512
#define DD 64
#define HWSZ 4096
#define CCH 64
#define NFLAT 131072
#define NTILES 1024            // NFLAT / 128
#define NCTA 148
#define TPB 512

#define LOSS_OFF   0ULL
#define QOUT_OFF   1ULL
#define PERP_OFF   8388609ULL
#define ENC_OFF    8388610ULL   // elem offset == 2 (mod 4)
#define QFLAT_OFF  75497474ULL  // elem offset == 2 (mod 4)

#define TAU_GAP  6e-4f
#define TAU_BAND 2.4e-3f

// ---- dynamic smem byte offsets ----
#define SM_HIST  0              // 512 int
#define SM_SSE   2048           // double
#define SM_FLAG  2056           // unsigned
#define SM_HN    2176           // 512 float
#define SM_BEST  4224           // 128 rows x 8 slots float
#define SM_BEST2 8320
#define SM_IDX   12416
#define SM_X0    16512          // 128 x 66 fp32 = 33792 B
#define SM_X1    50304
#define SM_BHI   84096          // 512 x 144B bf16
#define SM_BLO   157824
#define SM_BIDX  231552         // 128 int
#define SM_TOTAL 232064

#define XSTR 66
#define BSTR 144

__device__ int      g_hist_part[NCTA][KK];
__device__ double   g_sse_part[NCTA];
__device__ unsigned g_done;

__device__ __forceinline__ uint32_t smem_u32(const void* p) {
    uint32_t a;
    asm("{ .reg .u64 t; cvta.to.shared.u64 t, %1; cvt.u32.u64 %0, t; }" : "=r"(a) : "l"(p));
    return a;
}
__device__ __forceinline__ void ldsm_x4(uint32_t* r, uint32_t addr) {
    asm volatile("ldmatrix.sync.aligned.m8n8.x4.shared.b16 {%0,%1,%2,%3}, [%4];"
                 : "=r"(r[0]), "=r"(r[1]), "=r"(r[2]), "=r"(r[3]) : "r"(addr));
}
__device__ __forceinline__ void mma_bf16(float& c0, float& c1, float& c2, float& c3,
                                         uint32_t a0, uint32_t a1, uint32_t a2, uint32_t a3,
                                         uint32_t b0, uint32_t b1) {
    asm("mma.sync.aligned.m16n8k16.row.col.f32.bf16.bf16.f32 "
        "{%0,%1,%2,%3}, {%4,%5,%6,%7}, {%8,%9}, {%0,%1,%2,%3};"
        : "+f"(c0), "+f"(c1), "+f"(c2), "+f"(c3)
        : "r"(a0), "r"(a1), "r"(a2), "r"(a3), "r"(b0), "r"(b1));
}
__device__ __forceinline__ void cp_async4(uint32_t dst, const void* src) {
    asm volatile("cp.async.ca.shared.global [%0], [%1], 4;" :: "r"(dst), "l"(src));
}
__device__ __forceinline__ void cp_wait_all() {
    asm volatile("cp.async.wait_all;" ::: "memory");
}
__device__ __forceinline__ void split_pair(float f0, float f1, uint32_t& hi, uint32_t& lo) {
    __nv_bfloat16 h0 = __float2bfloat16_rn(f0), h1 = __float2bfloat16_rn(f1);
    hi = ((uint32_t)__bfloat16_as_ushort(h1) << 16) | (uint32_t)__bfloat16_as_ushort(h0);
    float r0 = f0 - __bfloat162float(h0), r1 = f1 - __bfloat162float(h1);
    __nv_bfloat16 l0 = __float2bfloat16_rn(r0), l1 = __float2bfloat16_rn(r1);
    lo = ((uint32_t)__bfloat16_as_ushort(l1) << 16) | (uint32_t)__bfloat16_as_ushort(l0);
}
#define UPD(b, b2, i, s, n) { bool p_ = (s) > (b); \
    (b2) = p_ ? (b) : fmaxf((b2), (s)); (i) = p_ ? (n) : (i); (b) = p_ ? (s) : (b); }

// ================= single fused kernel =================
__global__ __launch_bounds__(TPB, 1)
void vq_mma_kernel(const float* __restrict__ in,
                   const float* __restrict__ emb,
                   float* __restrict__ out)
{
    extern __shared__ __align__(128) char smem[];
    const uint32_t sb = smem_u32(smem);
    const int tid  = threadIdx.x;
    const int cta  = blockIdx.x;
    const int lane = tid & 31;
    const int w    = tid >> 5;
    const int half = w >> 3;
    const int grp  = lane >> 2;
    const int tig  = lane & 3;
    const int rowA = (w & 7) * 16 + grp;
    const int rowB = rowA + 8;
    const int wr   = tid >> 2;         // write-out row
    const int wsub = tid & 3;          // write-out dim quarter

    const uint32_t bofs = (uint32_t)((lane & 7) + ((lane >> 4) & 1) * 8) * BSTR
                        + (uint32_t)((lane >> 3) & 1) * 16;

    int*    shist  = (int*)(smem + SM_HIST);
    float*  shn    = (float*)(smem + SM_HN);
    float*  sBest  = (float*)(smem + SM_BEST);
    float*  sBest2 = (float*)(smem + SM_BEST2);
    int*    sIdx   = (int*)(smem + SM_IDX);
    int*    sBidx  = (int*)(smem + SM_BIDX);
    float*  sXb[2] = { (float*)(smem + SM_X0), (float*)(smem + SM_X1) };

    for (int i = tid; i < KK; i += TPB) shist[i] = 0;
    if (tid == 0) *(double*)(smem + SM_SSE) = 0.0;

    // ---- codebook -> SMEM bf16 hi/lo (once) ----
    for (int i = tid; i < KK * 16; i += TPB) {
        float4 v = __ldg((const float4*)emb + i);
        int r = i >> 4, c4 = i & 15;
        uint32_t h0, l0, h1, l1;
        split_pair(v.x, v.y, h0, l0);
        split_pair(v.z, v.w, h1, l1);
        *(uint2*)(smem + SM_BHI + r * BSTR + c4 * 8) = make_uint2(h0, h1);
        *(uint2*)(smem + SM_BLO + r * BSTR + c4 * 8) = make_uint2(l0, l1);
    }
    for (int r = tid; r < KK; r += TPB) {
        const float4* e4 = (const float4*)(emb + (size_t)r * DD);
        float acc = 0.f;
        #pragma unroll
        for (int j = 0; j < 16; j++) {
            float4 q = __ldg(e4 + j);
            acc = fmaf(q.x, q.x, acc); acc = fmaf(q.y, q.y, acc);
            acc = fmaf(q.z, q.z, acc); acc = fmaf(q.w, q.w, acc);
        }
        shn[r] = 0.5f * acc;
    }

    // ---- prologue: first X tile into buf 0 ----
    if (cta < NTILES) {
        const int n0g = cta << 7;
        const float* base = in + (size_t)(n0g >> 12) * CCH * HWSZ + (n0g & 4095);
        float* sX = sXb[0];
        for (int i = tid; i < 128 * DD; i += TPB) {
            int d = i >> 7, r = i & 127;
            sX[r * XSTR + d] = __ldg(base + (size_t)d * HWSZ + r);
        }
    }
    __syncthreads();

    // previous-tile write-out state
    int    prev_n0g = -1;
    float* prevX    = sXb[0];
    float  sse_acc  = 0.f;
    int    wb       = 0;      // cached sBidx[wr] for prev tile

    int p = 0;
    for (int tile = cta; tile < NTILES; tile += NCTA, p ^= 1) {
        const int n0g = tile << 7;
        float* sX = sXb[p];

        const int  nt       = tile + NCTA;
        const bool nt_valid = (nt < NTILES);
        const float* nbase  = nt_valid
            ? in + (size_t)((nt << 7) >> 12) * CCH * HWSZ + ((nt << 7) & 4095) : nullptr;
        const uint32_t sxn  = sb + ((p ^ 1) ? SM_X1 : SM_X0);

        float*  ep  = out + ENC_OFF + (size_t)n0g * KK;
        float4* e4z = (float4*)(ep + 2);
        const float4 z4 = make_float4(0.f, 0.f, 0.f, 0.f);
        if (tid == 0)   *(float2*)ep = make_float2(0.f, 0.f);
        if (tid == 128) *(float2*)(ep + 2 + 16383 * 4) = make_float2(0.f, 0.f);

        // ---- build A fragments (hi/lo) from sX ----
        uint32_t ah[4][4], al[4][4];
        #pragma unroll
        for (int kb = 0; kb < 4; kb++) {
            int k = kb * 16 + tig * 2;
            float2 p00 = *(const float2*)(sX + rowA * XSTR + k);
            float2 p10 = *(const float2*)(sX + rowB * XSTR + k);
            float2 p01 = *(const float2*)(sX + rowA * XSTR + k + 8);
            float2 p11 = *(const float2*)(sX + rowB * XSTR + k + 8);
            split_pair(p00.x, p00.y, ah[kb][0], al[kb][0]);
            split_pair(p10.x, p10.y, ah[kb][1], al[kb][1]);
            split_pair(p01.x, p01.y, ah[kb][2], al[kb][2]);
            split_pair(p11.x, p11.y, ah[kb][3], al[kb][3]);
        }

        // ---- scan 256 codes + interleaved enc-zero + prev write-out + X prefetch ----
        float bestA = -3.4e38f, best2A = -3.4e38f;
        float bestB = -3.4e38f, best2B = -3.4e38f;
        int idxA = 0, idxB = 0;
        #pragma unroll 1
        for (int np = 0; np < 16; np++) {
            // enc-zero: 2 float4 per thread per iteration
            {
                int i = (np * TPB + tid) * 2;
                if (i < 16383)     __stcs(e4z + i, z4);
                if (i + 1 < 16383) __stcs(e4z + i + 1, z4);
            }
            if (np < 8) {
                // ---- write-out chunk for PREVIOUS tile (2 dims/thread) ----
                if (prev_n0g >= 0) {
                    if (np == 0) wb = sBidx[wr];
                    const int c0 = wsub * 16 + np * 2;
                    float2 ee = __ldg((const float2*)(emb + (size_t)wb * DD + c0));
                    const float* xr = prevX + wr * XSTR + c0;
                    float d0 = xr[0] - ee.x, d1 = xr[1] - ee.y;
                    sse_acc = fmaf(d0, d0, fmaf(d1, d1, sse_acc));

                    const int pb = prev_n0g >> 12, phw = prev_n0g & 4095;
                    float* qo = out + QOUT_OFF + (size_t)pb * CCH * HWSZ + phw + wr;
                    __stcs(qo + (size_t)c0 * HWSZ, ee.x);
                    __stcs(qo + (size_t)(c0 + 1) * HWSZ, ee.y);
                    float* qf = out + QFLAT_OFF + (size_t)(prev_n0g + wr) * DD + c0;
                    __stcs((float2*)qf, ee);   // offset ≡ 2 mod 4 elems -> 8B aligned

                    if (np == 7) {
                        if (wsub == 0) {
                            __stcs(out + ENC_OFF + (size_t)(prev_n0g + wr) * KK + wb, 1.0f);
                            atomicAdd(&shist[wb], 1);
                        }
                        #pragma unroll
                        for (int off = 16; off; off >>= 1)
                            sse_acc += __shfl_xor_sync(0xFFFFFFFFu, sse_acc, off);
                        if (lane == 0)
                            atomicAdd((double*)(smem + SM_SSE), (double)sse_acc);
                        sse_acc = 0.f;
                    }
                }
            } else {
                if (np == 8) __syncthreads();   // prev-X reads done before overwrite
                if (nt_valid) {
                    int i = (np - 8) * 1024 + tid;
                    int d1i = i >> 7, r1i = i & 127;
                    cp_async4(sxn + (uint32_t)(r1i * XSTR + d1i) * 4,
                              nbase + (size_t)d1i * HWSZ + r1i);
                    i += 512;
                    int d2i = i >> 7, r2i = i & 127;
                    cp_async4(sxn + (uint32_t)(r2i * XSTR + d2i) * 4,
                              nbase + (size_t)d2i * HWSZ + r2i);
                }
            }

            uint32_t base = sb + SM_BHI + (uint32_t)(half * 256 + np * 16) * BSTR + bofs;
            uint32_t bh[4][4], bl[4][4];
            #pragma unroll
            for (int kb = 0; kb < 4; kb++) ldsm_x4(bh[kb], base + kb * 32);
            #pragma unroll
            for (int kb = 0; kb < 4; kb++) ldsm_x4(bl[kb], base + kb * 32 + (SM_BLO - SM_BHI));
            #pragma unroll
            for (int h = 0; h < 2; h++) {
                float c0 = 0.f, c1 = 0.f, c2 = 0.f, c3 = 0.f;
                #pragma unroll
                for (int kb = 0; kb < 4; kb++)
                    mma_bf16(c0,c1,c2,c3, ah[kb][0],ah[kb][1],ah[kb][2],ah[kb][3],
                             bh[kb][2*h], bh[kb][2*h+1]);
                #pragma unroll
                for (int kb = 0; kb < 4; kb++)
                    mma_bf16(c0,c1,c2,c3, ah[kb][0],ah[kb][1],ah[kb][2],ah[kb][3],
                             bl[kb][2*h], bl[kb][2*h+1]);
                #pragma unroll
                for (int kb = 0; kb < 4; kb++)
                    mma_bf16(c0,c1,c2,c3, al[kb][0],al[kb][1],al[kb][2],al[kb][3],
                             bh[kb][2*h], bh[kb][2*h+1]);
                int ncol = half * 256 + np * 16 + h * 8 + tig * 2;
                float2 hn2 = *(const float2*)(shn + ncol);
                float s0 = c0 - hn2.x, s1 = c1 - hn2.y;
                float s2 = c2 - hn2.x, s3 = c3 - hn2.y;
                UPD(bestA, best2A, idxA, s0, ncol);
                UPD(bestA, best2A, idxA, s1, ncol + 1);
                UPD(bestB, best2B, idxB, s2, ncol);
                UPD(bestB, best2B, idxB, s3, ncol + 1);
            }
        }
        const int slot = half * 4 + tig;
        sBest [rowA * 8 + slot] = bestA;  sBest [rowB * 8 + slot] = bestB;
        sBest2[rowA * 8 + slot] = best2A; sBest2[rowB * 8 + slot] = best2B;
        sIdx  [rowA * 8 + slot] = idxA;   sIdx  [rowB * 8 + slot] = idxB;
        __syncthreads();

        // ---- combine + rare exact re-resolve (tid<128, one thread/row) ----
        if (tid < 128) {
            const int r = tid;
            float best = -3.4e38f, b2 = -3.4e38f;
            int bidx = 0;
            #pragma unroll
            for (int t = 0; t < 8; t++) {
                float bb = sBest[r * 8 + t], bb2 = sBest2[r * 8 + t];
                int   ii = sIdx[r * 8 + t];
                if (bb > best) { b2 = fmaxf(best, bb2); best = bb; bidx = ii; }
                else           { b2 = fmaxf(b2, bb); }
            }

            unsigned needmask = __ballot_sync(0xFFFFFFFFu, best - b2 < TAU_GAP);
            while (needmask) {
                const int src = __ffs(needmask) - 1;
                needmask &= needmask - 1;
                const int rsel = (tid & ~31) | src;
                const float cut = __shfl_sync(0xFFFFFFFFu, best, src) - TAU_BAND;
                const float* xr = sX + rsel * XSTR;
                double bd = 1e300; int bi = KK;
                #pragma unroll 1
                for (int kk = 0; kk < 16; kk++) {
                    const int k = lane * 16 + kk;
                    const float4* e4 = (const float4*)(emb + (size_t)k * DD);
                    float a0 = 0.f, a1 = 0.f, a2 = 0.f, a3 = 0.f;
                    #pragma unroll
                    for (int j = 0; j < 16; j++) {
                        float4 q = __ldg(e4 + j);
                        a0 = fmaf(xr[4*j+0], q.x, a0);
                        a1 = fmaf(xr[4*j+1], q.y, a1);
                        a2 = fmaf(xr[4*j+2], q.z, a2);
                        a3 = fmaf(xr[4*j+3], q.w, a3);
                    }
                    float s = (a0 + a1) + (a2 + a3) - shn[k];
                    if (s > cut) {
                        const float* e = emb + (size_t)k * DD;
                        double d0 = 0.0, d1 = 0.0;
                        #pragma unroll
                        for (int j = 0; j < 32; j++) {
                            double f0 = (double)xr[2*j]   - (double)__ldg(e + 2*j);
                            double f1 = (double)xr[2*j+1] - (double)__ldg(e + 2*j+1);
                            d0 = fma(f0, f0, d0);
                            d1 = fma(f1, f1, d1);
                        }
                        double dd = d0 + d1;
                        if (dd < bd || (dd == bd && k < bi)) { bd = dd; bi = k; }
                    }
                }
                #pragma unroll
                for (int off = 16; off; off >>= 1) {
                    double obd = __shfl_xor_sync(0xFFFFFFFFu, bd, off);
                    int    obi = __shfl_xor_sync(0xFFFFFFFFu, bi, off);
                    if (obd < bd || (obd == bd && obi < bi)) { bd = obd; bi = obi; }
                }
                if (lane == src) bidx = bi;
            }
            sBidx[r] = bidx;
        }

        prev_n0g = n0g;
        prevX    = sX;
        cp_wait_all();
        __syncthreads();   // sBidx visible; next-tile X complete
    }

    // ---- final tile write-out (standalone) ----
    if (prev_n0g >= 0) {
        wb = sBidx[wr];
        const int pb = prev_n0g >> 12, phw = prev_n0g & 4095;
        const float* xr = prevX + wr * XSTR + wsub * 16;
        float* qo = out + QOUT_OFF + (size_t)pb * CCH * HWSZ + phw + wr;
        float* qf = out + QFLAT_OFF + (size_t)(prev_n0g + wr) * DD + wsub * 16;
        sse_acc = 0.f;
        #pragma unroll
        for (int j = 0; j < 8; j++) {
            const int c0 = wsub * 16 + j * 2;
            float2 ee = __ldg((const float2*)(emb + (size_t)wb * DD + c0));
            float d0 = xr[2*j] - ee.x, d1 = xr[2*j+1] - ee.y;
            sse_acc = fmaf(d0, d0, fmaf(d1, d1, sse_acc));
            __stcs(qo + (size_t)c0 * HWSZ, ee.x);
            __stcs(qo + (size_t)(c0 + 1) * HWSZ, ee.y);
            __stcs((float2*)(qf + 2*j), ee);
        }
        if (wsub == 0) {
            __stcs(out + ENC_OFF + (size_t)(prev_n0g + wr) * KK + wb, 1.0f);
            atomicAdd(&shist[wb], 1);
        }
        #pragma unroll
        for (int off = 16; off; off >>= 1)
            sse_acc += __shfl_xor_sync(0xFFFFFFFFu, sse_acc, off);
        if (lane == 0) atomicAdd((double*)(smem + SM_SSE), (double)sse_acc);
    }
    __syncthreads();

    // ---- per-CTA flush ----
    for (int i = tid; i < KK; i += TPB) g_hist_part[cta][i] = shist[i];
    if (tid == 0) g_sse_part[cta] = *(double*)(smem + SM_SSE);
    __threadfence();
    __syncthreads();
    if (tid == 0) *(unsigned*)(smem + SM_FLAG) = atomicAdd(&g_done, 1u);
    __syncthreads();

    // ---- last CTA finalizes ----
    if (*(unsigned*)(smem + SM_FLAG) == NCTA - 1) {
        float* red = (float*)(smem + SM_BEST);
        int s = 0;
        for (int c = 0; c < NCTA; c++) s += g_hist_part[c][tid];
        float pr = (float)s / (float)NFLAT;
        red[tid] = pr * logf(pr + 1e-10f);
        __syncthreads();
        #pragma unroll
        for (int st = 256; st; st >>= 1) {
            if (tid < st) red[tid] += red[tid + st];
            __syncthreads();
        }
        if (tid == 0) {
            double a = 0.0;
            for (int c = 0; c < NCTA; c++) a += g_sse_part[c];
            out[PERP_OFF] = expf(-red[0]);
            out[LOSS_OFF] = 0.25f * (float)(a / ((double)NFLAT * (double)DD));
            g_done = 0;
        }
    }
}

extern "C" void kernel_launch(void* const* d_in, const int* in_sizes, int n_in,
                              void* d_out, int out_size)
{
    const float* in  = (const float*)d_in[0];
    const float* emb = (const float*)d_in[1];
    float* out = (float*)d_out;

    cudaFuncSetAttribute(vq_mma_kernel,
                         cudaFuncAttributeMaxDynamicSharedMemorySize, SM_TOTAL);
    vq_mma_kernel<<<NCTA, TPB, SM_TOTAL>>>(in, emb, out);
}

// round 10
// speedup vs baseline: 1.5985x; 1.5985x over previous
#include <cuda_runtime.h>
#include <cuda_bf16.h>
#include <cstdint>

#define KK 512
#define DD 64
#define HWSZ 4096
#define CCH 64
#define NFLAT 131072
#define NTILES 1024            // NFLAT / 128
#define NCTA 148
#define TPB 512

#define LOSS_OFF   0ULL
#define QOUT_OFF   1ULL
#define PERP_OFF   8388609ULL
#define ENC_OFF    8388610ULL   // elem offset == 2 (mod 4)
#define QFLAT_OFF  75497474ULL  // elem offset == 2 (mod 4)

#define TAU_GAP  6e-4f
#define TAU_BAND 2.4e-3f

// ---- dynamic smem byte offsets ----
#define SM_HIST  0              // 512 int
#define SM_SSE   2048           // double
#define SM_FLAG  2056           // unsigned
#define SM_HN    2176           // 512 float
#define SM_BEST  4224           // 128 rows x 8 slots float
#define SM_BEST2 8320
#define SM_IDX   12416
#define SM_X0    16512          // 128 x 66 fp32 = 33792 B
#define SM_X1    50304
#define SM_BHI   84096          // 512 x 144B bf16
#define SM_BLO   157824
#define SM_BIDX  231552         // 128 int
#define SM_TOTAL 232064

#define XSTR 66
#define BSTR 144

__device__ int      g_hist_part[NCTA][KK];
__device__ double   g_sse_part[NCTA];
__device__ unsigned g_done;

__device__ __forceinline__ uint32_t smem_u32(const void* p) {
    uint32_t a;
    asm("{ .reg .u64 t; cvta.to.shared.u64 t, %1; cvt.u32.u64 %0, t; }" : "=r"(a) : "l"(p));
    return a;
}
// NON-volatile ldmatrix: ONLY for the immutable B tiles (written once before
// the persistent loop). Lets ptxas software-pipeline B loads across np iters.
__device__ __forceinline__ void ldsm_x4_nv(uint32_t* r, uint32_t addr) {
    asm("ldmatrix.sync.aligned.m8n8.x4.shared.b16 {%0,%1,%2,%3}, [%4];"
        : "=r"(r[0]), "=r"(r[1]), "=r"(r[2]), "=r"(r[3]) : "r"(addr));
}
__device__ __forceinline__ void mma_bf16(float& c0, float& c1, float& c2, float& c3,
                                         uint32_t a0, uint32_t a1, uint32_t a2, uint32_t a3,
                                         uint32_t b0, uint32_t b1) {
    asm("mma.sync.aligned.m16n8k16.row.col.f32.bf16.bf16.f32 "
        "{%0,%1,%2,%3}, {%4,%5,%6,%7}, {%8,%9}, {%0,%1,%2,%3};"
        : "+f"(c0), "+f"(c1), "+f"(c2), "+f"(c3)
        : "r"(a0), "r"(a1), "r"(a2), "r"(a3), "r"(b0), "r"(b1));
}
__device__ __forceinline__ void cp_async4(uint32_t dst, const void* src) {
    asm volatile("cp.async.ca.shared.global [%0], [%1], 4;" :: "r"(dst), "l"(src));
}
__device__ __forceinline__ void cp_wait_all() {
    asm volatile("cp.async.wait_all;" ::: "memory");
}
__device__ __forceinline__ void split_pair(float f0, float f1, uint32_t& hi, uint32_t& lo) {
    __nv_bfloat16 h0 = __float2bfloat16_rn(f0), h1 = __float2bfloat16_rn(f1);
    hi = ((uint32_t)__bfloat16_as_ushort(h1) << 16) | (uint32_t)__bfloat16_as_ushort(h0);
    float r0 = f0 - __bfloat162float(h0), r1 = f1 - __bfloat162float(h1);
    __nv_bfloat16 l0 = __float2bfloat16_rn(r0), l1 = __float2bfloat16_rn(r1);
    lo = ((uint32_t)__bfloat16_as_ushort(l1) << 16) | (uint32_t)__bfloat16_as_ushort(l0);
}
#define UPD(b, b2, i, s, n) { bool p_ = (s) > (b); \
    (b2) = p_ ? (b) : fmaxf((b2), (s)); (i) = p_ ? (n) : (i); (b) = p_ ? (s) : (b); }

// ================= single fused kernel =================
__global__ __launch_bounds__(TPB, 1)
void vq_mma_kernel(const float* __restrict__ in,
                   const float* __restrict__ emb,
                   float* __restrict__ out)
{
    extern __shared__ __align__(128) char smem[];
    const uint32_t sb = smem_u32(smem);
    const int tid  = threadIdx.x;
    const int cta  = blockIdx.x;
    const int lane = tid & 31;
    const int w    = tid >> 5;
    const int half = w >> 3;
    const int grp  = lane >> 2;
    const int tig  = lane & 3;
    const int rowA = (w & 7) * 16 + grp;
    const int rowB = rowA + 8;

    const uint32_t bofs = (uint32_t)((lane & 7) + ((lane >> 4) & 1) * 8) * BSTR
                        + (uint32_t)((lane >> 3) & 1) * 16;

    int*    shist  = (int*)(smem + SM_HIST);
    float*  shn    = (float*)(smem + SM_HN);
    float*  sBest  = (float*)(smem + SM_BEST);
    float*  sBest2 = (float*)(smem + SM_BEST2);
    int*    sIdx   = (int*)(smem + SM_IDX);
    int*    sBidx  = (int*)(smem + SM_BIDX);
    float*  sXb[2] = { (float*)(smem + SM_X0), (float*)(smem + SM_X1) };

    for (int i = tid; i < KK; i += TPB) shist[i] = 0;
    if (tid == 0) *(double*)(smem + SM_SSE) = 0.0;

    // ---- codebook -> SMEM bf16 hi/lo (once; immutable afterwards) ----
    for (int i = tid; i < KK * 16; i += TPB) {
        float4 v = __ldg((const float4*)emb + i);
        int r = i >> 4, c4 = i & 15;
        uint32_t h0, l0, h1, l1;
        split_pair(v.x, v.y, h0, l0);
        split_pair(v.z, v.w, h1, l1);
        *(uint2*)(smem + SM_BHI + r * BSTR + c4 * 8) = make_uint2(h0, h1);
        *(uint2*)(smem + SM_BLO + r * BSTR + c4 * 8) = make_uint2(l0, l1);
    }
    for (int r = tid; r < KK; r += TPB) {
        const float4* e4 = (const float4*)(emb + (size_t)r * DD);
        float acc = 0.f;
        #pragma unroll
        for (int j = 0; j < 16; j++) {
            float4 q = __ldg(e4 + j);
            acc = fmaf(q.x, q.x, acc); acc = fmaf(q.y, q.y, acc);
            acc = fmaf(q.z, q.z, acc); acc = fmaf(q.w, q.w, acc);
        }
        shn[r] = 0.5f * acc;
    }

    // ---- prologue: first X tile into buf 0 ----
    if (cta < NTILES) {
        const int n0g = cta << 7;
        const float* base = in + (size_t)(n0g >> 12) * CCH * HWSZ + (n0g & 4095);
        float* sX = sXb[0];
        for (int i = tid; i < 128 * DD; i += TPB) {
            int d = i >> 7, r = i & 127;
            sX[r * XSTR + d] = __ldg(base + (size_t)d * HWSZ + r);
        }
    }
    __syncthreads();

    int p = 0;
    for (int tile = cta; tile < NTILES; tile += NCTA, p ^= 1) {
        const int n0g = tile << 7;
        const int b   = n0g >> 12;
        const int hw0 = n0g & 4095;
        float* sX = sXb[p];

        const int  nt       = tile + NCTA;
        const bool nt_valid = (nt < NTILES);
        const float* nbase  = nt_valid
            ? in + (size_t)((nt << 7) >> 12) * CCH * HWSZ + ((nt << 7) & 4095) : nullptr;
        const uint32_t sxn  = sb + ((p ^ 1) ? SM_X1 : SM_X0);

        float*  ep  = out + ENC_OFF + (size_t)n0g * KK;
        float4* e4z = (float4*)(ep + 2);
        const float4 z4 = make_float4(0.f, 0.f, 0.f, 0.f);
        if (tid == 0)   *(float2*)ep = make_float2(0.f, 0.f);
        if (tid == 128) *(float2*)(ep + 2 + 16383 * 4) = make_float2(0.f, 0.f);

        // ---- build A fragments (hi/lo) from sX ----
        uint32_t ah[4][4], al[4][4];
        #pragma unroll
        for (int kb = 0; kb < 4; kb++) {
            int k = kb * 16 + tig * 2;
            float2 p00 = *(const float2*)(sX + rowA * XSTR + k);
            float2 p10 = *(const float2*)(sX + rowB * XSTR + k);
            float2 p01 = *(const float2*)(sX + rowA * XSTR + k + 8);
            float2 p11 = *(const float2*)(sX + rowB * XSTR + k + 8);
            split_pair(p00.x, p00.y, ah[kb][0], al[kb][0]);
            split_pair(p10.x, p10.y, ah[kb][1], al[kb][1]);
            split_pair(p01.x, p01.y, ah[kb][2], al[kb][2]);
            split_pair(p11.x, p11.y, ah[kb][3], al[kb][3]);
        }

        // ---- scan 256 codes + interleaved enc-zero + X prefetch ----
        float bestA = -3.4e38f, best2A = -3.4e38f;
        float bestB = -3.4e38f, best2B = -3.4e38f;
        int idxA = 0, idxB = 0;
        #pragma unroll 1
        for (int np = 0; np < 16; np++) {
            {
                int i = (np * TPB + tid) * 2;
                if (i < 16383)     __stcs(e4z + i, z4);
                if (i + 1 < 16383) __stcs(e4z + i + 1, z4);
            }
            if (nt_valid) {
                int i = np * TPB + tid;
                int d = i >> 7, r = i & 127;
                cp_async4(sxn + (uint32_t)(r * XSTR + d) * 4,
                          nbase + (size_t)d * HWSZ + r);
            }

            uint32_t base = sb + SM_BHI + (uint32_t)(half * 256 + np * 16) * BSTR + bofs;
            uint32_t bh[4][4], bl[4][4];
            #pragma unroll
            for (int kb = 0; kb < 4; kb++) ldsm_x4_nv(bh[kb], base + kb * 32);
            #pragma unroll
            for (int kb = 0; kb < 4; kb++) ldsm_x4_nv(bl[kb], base + kb * 32 + (SM_BLO - SM_BHI));
            #pragma unroll
            for (int h = 0; h < 2; h++) {
                float c0 = 0.f, c1 = 0.f, c2 = 0.f, c3 = 0.f;
                #pragma unroll
                for (int kb = 0; kb < 4; kb++)
                    mma_bf16(c0,c1,c2,c3, ah[kb][0],ah[kb][1],ah[kb][2],ah[kb][3],
                             bh[kb][2*h], bh[kb][2*h+1]);
                #pragma unroll
                for (int kb = 0; kb < 4; kb++)
                    mma_bf16(c0,c1,c2,c3, ah[kb][0],ah[kb][1],ah[kb][2],ah[kb][3],
                             bl[kb][2*h], bl[kb][2*h+1]);
                #pragma unroll
                for (int kb = 0; kb < 4; kb++)
                    mma_bf16(c0,c1,c2,c3, al[kb][0],al[kb][1],al[kb][2],al[kb][3],
                             bh[kb][2*h], bh[kb][2*h+1]);
                int ncol = half * 256 + np * 16 + h * 8 + tig * 2;
                float2 hn2 = *(const float2*)(shn + ncol);
                float s0 = c0 - hn2.x, s1 = c1 - hn2.y;
                float s2 = c2 - hn2.x, s3 = c3 - hn2.y;
                UPD(bestA, best2A, idxA, s0, ncol);
                UPD(bestA, best2A, idxA, s1, ncol + 1);
                UPD(bestB, best2B, idxB, s2, ncol);
                UPD(bestB, best2B, idxB, s3, ncol + 1);
            }
        }
        const int slot = half * 4 + tig;
        sBest [rowA * 8 + slot] = bestA;  sBest [rowB * 8 + slot] = bestB;
        sBest2[rowA * 8 + slot] = best2A; sBest2[rowB * 8 + slot] = best2B;
        sIdx  [rowA * 8 + slot] = idxA;   sIdx  [rowB * 8 + slot] = idxB;
        __syncthreads();

        // ---- combine + rare exact re-resolve: ALL 16 warps (row = tid>>2) ----
        {
            const int  r      = tid >> 2;
            const bool active = (tid & 3) == 0;
            float best = -3.4e38f, b2 = -3.4e38f;
            int bidx = 0;
            #pragma unroll
            for (int t = 0; t < 8; t++) {
                float bb = sBest[r * 8 + t], bb2 = sBest2[r * 8 + t];
                int   ii = sIdx[r * 8 + t];
                if (bb > best) { b2 = fmaxf(best, bb2); best = bb; bidx = ii; }
                else           { b2 = fmaxf(b2, bb); }
            }

            unsigned needmask = __ballot_sync(0xFFFFFFFFu,
                                              active && (best - b2 < TAU_GAP));
            while (needmask) {
                const int src = __ffs(needmask) - 1;
                needmask &= needmask - 1;
                const int   rneed = __shfl_sync(0xFFFFFFFFu, r, src);
                const float cut   = __shfl_sync(0xFFFFFFFFu, best, src) - TAU_BAND;
                const float* xr = sX + rneed * XSTR;
                double bd = 1e300; int bi = KK;
                #pragma unroll 1
                for (int kk = 0; kk < 16; kk++) {
                    const int k = lane * 16 + kk;
                    const float4* e4 = (const float4*)(emb + (size_t)k * DD);
                    float a0 = 0.f, a1 = 0.f, a2 = 0.f, a3 = 0.f;
                    #pragma unroll
                    for (int j = 0; j < 16; j++) {
                        float4 q = __ldg(e4 + j);
                        a0 = fmaf(xr[4*j+0], q.x, a0);
                        a1 = fmaf(xr[4*j+1], q.y, a1);
                        a2 = fmaf(xr[4*j+2], q.z, a2);
                        a3 = fmaf(xr[4*j+3], q.w, a3);
                    }
                    float s = (a0 + a1) + (a2 + a3) - shn[k];
                    if (s > cut) {
                        const float* e = emb + (size_t)k * DD;
                        double d0 = 0.0, d1 = 0.0;
                        #pragma unroll
                        for (int j = 0; j < 32; j++) {
                            double f0 = (double)xr[2*j]   - (double)__ldg(e + 2*j);
                            double f1 = (double)xr[2*j+1] - (double)__ldg(e + 2*j+1);
                            d0 = fma(f0, f0, d0);
                            d1 = fma(f1, f1, d1);
                        }
                        double dd = d0 + d1;
                        if (dd < bd || (dd == bd && k < bi)) { bd = dd; bi = k; }
                    }
                }
                #pragma unroll
                for (int off = 16; off; off >>= 1) {
                    double obd = __shfl_xor_sync(0xFFFFFFFFu, bd, off);
                    int    obi = __shfl_xor_sync(0xFFFFFFFFu, bi, off);
                    if (obd < bd || (obd == bd && obi < bi)) { bd = obd; bi = obi; }
                }
                if (lane == src) bidx = bi;
            }
            if (active) sBidx[r] = bidx;
        }
        __syncthreads();

        // ---- parallel write-out: 4 threads per row, 16 dims each ----
        {
            const int r   = tid >> 2;
            const int sub = tid & 3;
            const int bidx = sBidx[r];
            const float* xr = sX + r * XSTR + sub * 16;

            float e[16];
            const float4* ep4 = (const float4*)(emb + (size_t)bidx * DD + sub * 16);
            #pragma unroll
            for (int j = 0; j < 4; j++) {
                float4 q = __ldg(ep4 + j);
                e[4*j] = q.x; e[4*j+1] = q.y; e[4*j+2] = q.z; e[4*j+3] = q.w;
            }
            float sse = 0.f;
            #pragma unroll
            for (int d = 0; d < 16; d++) { float df = xr[d] - e[d]; sse = fmaf(df, df, sse); }

            float* qo = out + QOUT_OFF + (size_t)b * CCH * HWSZ + hw0 + r
                        + (size_t)(sub * 16) * HWSZ;
            #pragma unroll
            for (int c = 0; c < 16; c++) __stcs(qo + (size_t)c * HWSZ, e[c]);

            float* qf = out + QFLAT_OFF + (size_t)(n0g + r) * DD + sub * 16; // ≡2 mod 4
            #pragma unroll
            for (int j = 0; j < 8; j++)
                __stcs((float2*)(qf + 2*j), make_float2(e[2*j], e[2*j+1]));

            if (sub == 0) {
                __stcs(ep + (size_t)r * KK + bidx, 1.0f);
                atomicAdd(&shist[bidx], 1);
            }
            #pragma unroll
            for (int off = 16; off; off >>= 1) sse += __shfl_xor_sync(0xFFFFFFFFu, sse, off);
            if (lane == 0) atomicAdd((double*)(smem + SM_SSE), (double)sse);
        }

        cp_wait_all();
        __syncthreads();
    }

    // ---- per-CTA flush ----
    for (int i = tid; i < KK; i += TPB) g_hist_part[cta][i] = shist[i];
    if (tid == 0) g_sse_part[cta] = *(double*)(smem + SM_SSE);
    __threadfence();
    __syncthreads();
    if (tid == 0) *(unsigned*)(smem + SM_FLAG) = atomicAdd(&g_done, 1u);
    __syncthreads();

    // ---- last CTA finalizes ----
    if (*(unsigned*)(smem + SM_FLAG) == NCTA - 1) {
        float* red = (float*)(smem + SM_BEST);
        int s = 0;
        for (int c = 0; c < NCTA; c++) s += g_hist_part[c][tid];
        float pr = (float)s / (float)NFLAT;
        red[tid] = pr * logf(pr + 1e-10f);
        __syncthreads();
        #pragma unroll
        for (int st = 256; st; st >>= 1) {
            if (tid < st) red[tid] += red[tid + st];
            __syncthreads();
        }
        if (tid == 0) {
            double a = 0.0;
            for (int c = 0; c < NCTA; c++) a += g_sse_part[c];
            out[PERP_OFF] = expf(-red[0]);
            out[LOSS_OFF] = 0.25f * (float)(a / ((double)NFLAT * (double)DD));
            g_done = 0;
        }
    }
}

extern "C" void kernel_launch(void* const* d_in, const int* in_sizes, int n_in,
                              void* d_out, int out_size)
{
    const float* in  = (const float*)d_in[0];
    const float* emb = (const float*)d_in[1];
    float* out = (float*)d_out;

    cudaFuncSetAttribute(vq_mma_kernel,
                         cudaFuncAttributeMaxDynamicSharedMemorySize, SM_TOTAL);
    vq_mma_kernel<<<NCTA, TPB, SM_TOTAL>>>(in, emb, out);
}